// round 10
// baseline (speedup 1.0000x reference)
#include <cuda_runtime.h>
#include <cuda_fp16.h>
#include <math.h>
#include <stdint.h>

// ---------------------------------------------------------------------------
// Problem shapes
// ---------------------------------------------------------------------------
#define B_  32
#define S_  2048
#define H_  1024
#define M_  (B_ * S_)
#define NCHUNK 16

// ---------------------------------------------------------------------------
// Device scratch (static: no allocations allowed)
// ---------------------------------------------------------------------------
__device__ float g_hproj[B_ * H_];
__device__ float g_scores[B_ * S_];
__device__ float g_ctx_part[B_ * NCHUNK * H_];
__device__ __half g_Ef16[(size_t)M_ * H_];     // 128 MB, single fp16 plane
__device__ __half g_Uhi[(size_t)H_ * H_];      // 2 MB
__device__ __half g_Ulo[(size_t)H_ * H_];      // 2 MB

// ---------------------------------------------------------------------------
// PTX helpers (baseline sm_100 ISA: cp.async, ldmatrix, mma.sync)
// ---------------------------------------------------------------------------
__device__ __forceinline__ uint32_t smem_u32(const void* p) {
    uint32_t a;
    asm("{ .reg .u64 t; cvta.to.shared.u64 t, %1; cvt.u32.u64 %0, t; }" : "=r"(a) : "l"(p));
    return a;
}

#define SMEM_SWIZZLE_128B(off) ((off) ^ (((off) >> 3) & 0x70))

__device__ __forceinline__ void cp_async16(uint32_t dst, const void* src) {
    asm volatile("cp.async.cg.shared.global [%0], [%1], 16;" :: "r"(dst), "l"(src));
}
#define CP_COMMIT() asm volatile("cp.async.commit_group;" ::: "memory")
template <int N>
__device__ __forceinline__ void cp_wait_group() {
    asm volatile("cp.async.wait_group %0;" :: "n"(N) : "memory");
}

__device__ __forceinline__ void ldmx4(uint32_t* r, uint32_t a) {
    asm volatile("ldmatrix.sync.aligned.m8n8.x4.shared.b16 {%0,%1,%2,%3}, [%4];"
                 : "=r"(r[0]), "=r"(r[1]), "=r"(r[2]), "=r"(r[3]) : "r"(a));
}
__device__ __forceinline__ void mma16816(float* d, const uint32_t* a, const uint32_t* b) {
    asm volatile(
        "mma.sync.aligned.m16n8k16.row.col.f32.f16.f16.f32 "
        "{%0,%1,%2,%3},{%4,%5,%6,%7},{%8,%9},{%0,%1,%2,%3};"
        : "+f"(d[0]), "+f"(d[1]), "+f"(d[2]), "+f"(d[3])
        : "r"(a[0]), "r"(a[1]), "r"(a[2]), "r"(a[3]), "r"(b[0]), "r"(b[1]));
}

// ---------------------------------------------------------------------------
// Kernel 0: zero score accumulator
// ---------------------------------------------------------------------------
__global__ void zero_scores_kernel() {
    int i = blockIdx.x * blockDim.x + threadIdx.x;
    if (i < B_ * S_) g_scores[i] = 0.0f;
}

// ---------------------------------------------------------------------------
// Converts: E -> single fp16 plane; U -> fp16 hi/lo split
// ---------------------------------------------------------------------------
__global__ void convert_E_kernel(const float* __restrict__ E) {
    size_t i = ((size_t)blockIdx.x * blockDim.x + threadIdx.x) * 4;
    float4 v = *(const float4*)(E + i);
    __half2* d = (__half2*)(g_Ef16 + i);
    d[0] = __floats2half2_rn(v.x, v.y);
    d[1] = __floats2half2_rn(v.z, v.w);
}

__global__ void convert_U_kernel(const float* __restrict__ U) {
    size_t i = ((size_t)blockIdx.x * blockDim.x + threadIdx.x) * 4;
    float4 v = *(const float4*)(U + i);
    float x[4] = {v.x, v.y, v.z, v.w};
    __half h[4], l[4];
    #pragma unroll
    for (int j = 0; j < 4; j++) {
        h[j] = __float2half_rn(x[j]);
        l[j] = __float2half_rn(x[j] - __half2float(h[j]));
    }
    __half2* dh = (__half2*)(g_Uhi + i);
    __half2* dl = (__half2*)(g_Ulo + i);
    dh[0] = __halves2half2(h[0], h[1]); dh[1] = __halves2half2(h[2], h[3]);
    dl[0] = __halves2half2(l[0], l[1]); dl[1] = __halves2half2(l[2], l[3]);
}

// ---------------------------------------------------------------------------
// Kernel 1: h_proj[b,k] = hidden[b,:] . W_w[k,:] + W_b[k]
// grid (8 k-slices, 32 batches), 256 threads, warp-per-k reduction.
// ---------------------------------------------------------------------------
__global__ void hproj_kernel(const float* __restrict__ hidden,
                             const float* __restrict__ W_w,
                             const float* __restrict__ W_b) {
    int slice = blockIdx.x;
    int b     = blockIdx.y;
    __shared__ float sh[H_];
    for (int i = threadIdx.x; i < H_; i += blockDim.x) sh[i] = hidden[b * H_ + i];
    __syncthreads();
    int warp = threadIdx.x >> 5, lane = threadIdx.x & 31;
    for (int kk = warp; kk < 128; kk += 8) {
        int k = slice * 128 + kk;
        const float* w = W_w + (size_t)k * H_;
        float s = 0.0f;
        #pragma unroll 8
        for (int h = lane; h < H_; h += 32) s += sh[h] * w[h];
        #pragma unroll
        for (int o = 16; o > 0; o >>= 1) s += __shfl_down_sync(0xffffffffu, s, o);
        if (lane == 0) g_hproj[b * H_ + k] = s + W_b[k];
    }
}

// ---------------------------------------------------------------------------
// Kernel 2: fp16 2-MMA score GEMM + fused tanh/V epilogue.
//   C[m,n] = E_f16[m,:] . (U_hi[n,:] + U_lo[n,:])   (fp32 accumulate)
//   score[m] += sum_n V_w[n] * tanh(C[m,n] + hproj[b,n] + U_b[n])
// Tile 128x128, BK=64, 4-stage cp.async, 256 threads (8 warps, 4x2, 32x64
// warp tile). MMAs ordered as full-bh pass then full-bl pass per kk so each
// accumulator's two updates are 16 MMAs apart (covers HMMA RAW latency).
// ---------------------------------------------------------------------------
#define BKC    64
#define NKCH   (H_ / BKC)         // 16
#define PLANE  16384              // 128 rows x 128 bytes (64 halves)
#define STG_SZ (3 * PLANE)        // A(E), Bh, Bl
#define NSTG   4
#define SMEM_GEMM (NSTG * STG_SZ) // 196608 B

extern __shared__ char dyn_smem[];

__device__ __forceinline__ void gemm_load_stage(uint32_t stg, int chunk,
                                                int m0, int n0, int tid) {
    const size_t kbase = (size_t)chunk * BKC;
    #pragma unroll
    for (int i = 0; i < 4; i++) {
        int p   = tid + i * 256;       // 0..1023
        int r   = p >> 3;              // row 0..127
        int c16 = p & 7;               // 16B piece 0..7
        uint32_t sw = SMEM_SWIZZLE_128B((uint32_t)(r * 128 + c16 * 16));
        size_t ga = (size_t)(m0 + r) * H_ + kbase + c16 * 8;
        size_t gb = (size_t)(n0 + r) * H_ + kbase + c16 * 8;
        cp_async16(stg + 0 * PLANE + sw, g_Ef16 + ga);
        cp_async16(stg + 1 * PLANE + sw, g_Uhi + gb);
        cp_async16(stg + 2 * PLANE + sw, g_Ulo + gb);
    }
    CP_COMMIT();
}

__global__ void __launch_bounds__(256, 1)
score_gemm_mma(const float* __restrict__ U_b, const float* __restrict__ V_w) {
    __shared__ float hp[128];
    __shared__ float vs[128];
    __shared__ float red[128][2];

    const int tid  = threadIdx.x;
    const int lane = tid & 31;
    const int wid  = tid >> 5;
    const int wm   = wid & 3;          // 4 m-warps, 32 rows each
    const int wn   = wid >> 2;         // 2 n-warps, 64 cols each
    const int n0   = blockIdx.x * 128;
    const int m0   = blockIdx.y * 128;
    const int b    = m0 >> 11;

    const uint32_t sbase = smem_u32(dyn_smem);

    if (tid < 128) {
        hp[tid] = g_hproj[b * H_ + n0 + tid] + U_b[n0 + tid];
        vs[tid] = V_w[n0 + tid];
    }

    float acc[2][8][4];
    #pragma unroll
    for (int mt = 0; mt < 2; mt++)
        #pragma unroll
        for (int nt = 0; nt < 8; nt++)
            #pragma unroll
            for (int q = 0; q < 4; q++) acc[mt][nt][q] = 0.0f;

    // prologue: chunks 0,1,2 into stages 0,1,2
    gemm_load_stage(sbase + 0 * STG_SZ, 0, m0, n0, tid);
    gemm_load_stage(sbase + 1 * STG_SZ, 1, m0, n0, tid);
    gemm_load_stage(sbase + 2 * STG_SZ, 2, m0, n0, tid);

    // A fragment offsets
    const uint32_t offA[2] = {
        SMEM_SWIZZLE_128B((uint32_t)((wm * 32 +  0 + (lane & 15)) * 128 + (lane >> 4) * 16)),
        SMEM_SWIZZLE_128B((uint32_t)((wm * 32 + 16 + (lane & 15)) * 128 + (lane >> 4) * 16))
    };
    // B fragment offsets for ldmatrix.x4: quad t covers n-tiles 2t, 2t+1.
    uint32_t offB4[4];
    #pragma unroll
    for (int t = 0; t < 4; t++) {
        uint32_t row = (uint32_t)(wn * 64 + t * 16 + ((lane >> 4) << 3) + (lane & 7));
        uint32_t piece = (lane >> 3) & 1;
        offB4[t] = SMEM_SWIZZLE_128B(row * 128 + piece * 16);
    }

    for (int c = 0; c < NKCH; c++) {
        if (c < NKCH - 2)       cp_wait_group<2>();
        else if (c == NKCH - 2) cp_wait_group<1>();
        else                    cp_wait_group<0>();
        __syncthreads();
        // Load AFTER the barrier: stage (c+3)%4 held chunk c-1, whose reads all
        // completed before this barrier.
        if (c + 3 < NKCH)
            gemm_load_stage(sbase + ((c + 3) % NSTG) * STG_SZ, c + 3, m0, n0, tid);

        const uint32_t stg = sbase + (uint32_t)((c % NSTG) * STG_SZ);
        #pragma unroll
        for (int kk = 0; kk < 4; kk++) {
            const uint32_t kb = (uint32_t)(kk * 32);
            uint32_t ah[2][4];
            #pragma unroll
            for (int mt = 0; mt < 2; mt++)
                ldmx4(ah[mt], stg + 0 * PLANE + (offA[mt] ^ kb));
            uint32_t bh[4][4], bl[4][4];
            #pragma unroll
            for (int t = 0; t < 4; t++) {
                ldmx4(bh[t], stg + 1 * PLANE + (offB4[t] ^ kb));
                ldmx4(bl[t], stg + 2 * PLANE + (offB4[t] ^ kb));
            }
            // Pass 1: all bh MMAs (16 independent accumulators)
            #pragma unroll
            for (int mt = 0; mt < 2; mt++)
                #pragma unroll
                for (int t = 0; t < 4; t++) {
                    mma16816(acc[mt][2 * t + 0], ah[mt], bh[t] + 0);
                    mma16816(acc[mt][2 * t + 1], ah[mt], bh[t] + 2);
                }
            // Pass 2: all bl MMAs (each acc's RAW is now 16 MMAs apart)
            #pragma unroll
            for (int mt = 0; mt < 2; mt++)
                #pragma unroll
                for (int t = 0; t < 4; t++) {
                    mma16816(acc[mt][2 * t + 0], ah[mt], bl[t] + 0);
                    mma16816(acc[mt][2 * t + 1], ah[mt], bl[t] + 2);
                }
        }
    }

    // Epilogue: tanh + V-weighted reduction.
    float part[2][2] = {{0.f, 0.f}, {0.f, 0.f}};
    #pragma unroll
    for (int mt = 0; mt < 2; mt++)
        #pragma unroll
        for (int nt = 0; nt < 8; nt++) {
            const int c0 = wn * 64 + nt * 8 + 2 * (lane & 3);
            const float* d = acc[mt][nt];
            part[mt][0] += tanhf(d[0] + hp[c0]) * vs[c0]
                         + tanhf(d[1] + hp[c0 + 1]) * vs[c0 + 1];
            part[mt][1] += tanhf(d[2] + hp[c0]) * vs[c0]
                         + tanhf(d[3] + hp[c0 + 1]) * vs[c0 + 1];
        }
    #pragma unroll
    for (int mt = 0; mt < 2; mt++)
        #pragma unroll
        for (int rr = 0; rr < 2; rr++) {
            float p = part[mt][rr];
            p += __shfl_xor_sync(0xffffffffu, p, 1);
            p += __shfl_xor_sync(0xffffffffu, p, 2);
            if ((lane & 3) == 0)
                red[wm * 32 + mt * 16 + rr * 8 + (lane >> 2)][wn] = p;
        }
    __syncthreads();
    if (tid < 128)
        atomicAdd(&g_scores[m0 + tid], red[tid][0] + red[tid][1]);
}

// ---------------------------------------------------------------------------
// Kernel 3: softmax over S per batch
// ---------------------------------------------------------------------------
__global__ void softmax_kernel(float* __restrict__ d_out) {
    const int b = blockIdx.x, tid = threadIdx.x;
    __shared__ float sred[256];
    float loc[8];
    float mx = -1e30f;
    #pragma unroll
    for (int q = 0; q < 8; q++) {
        loc[q] = g_scores[b * S_ + tid + q * 256];
        mx = fmaxf(mx, loc[q]);
    }
    sred[tid] = mx; __syncthreads();
    for (int o = 128; o > 0; o >>= 1) {
        if (tid < o) sred[tid] = fmaxf(sred[tid], sred[tid + o]);
        __syncthreads();
    }
    mx = sred[0]; __syncthreads();
    float sum = 0.0f;
    #pragma unroll
    for (int q = 0; q < 8; q++) { loc[q] = expf(loc[q] - mx); sum += loc[q]; }
    sred[tid] = sum; __syncthreads();
    for (int o = 128; o > 0; o >>= 1) {
        if (tid < o) sred[tid] += sred[tid + o];
        __syncthreads();
    }
    const float inv = 1.0f / sred[0];
    float* attn_out = d_out + B_ * H_;
    #pragma unroll
    for (int q = 0; q < 8; q++) {
        int s = tid + q * 256;
        float a = loc[q] * inv;
        attn_out[b * S_ + s] = a;
        g_scores[b * S_ + s] = a;
    }
}

// ---------------------------------------------------------------------------
// Kernels 4/5: context = attn @ E (partials + deterministic combine)
// ---------------------------------------------------------------------------
__global__ void context_partial_kernel(const float* __restrict__ E) {
    const int chunk = blockIdx.x, b = blockIdx.y, t = threadIdx.x;
    const int s0 = chunk * (S_ / NCHUNK);
    float4 acc = make_float4(0.f, 0.f, 0.f, 0.f);
    const float* base = E + (size_t)(b * S_ + s0) * H_ + t * 4;
    #pragma unroll 4
    for (int s = 0; s < S_ / NCHUNK; s++) {
        float a  = g_scores[b * S_ + s0 + s];
        float4 e = *(const float4*)(base + (size_t)s * H_);
        acc.x = fmaf(a, e.x, acc.x); acc.y = fmaf(a, e.y, acc.y);
        acc.z = fmaf(a, e.z, acc.z); acc.w = fmaf(a, e.w, acc.w);
    }
    *(float4*)&g_ctx_part[((size_t)(b * NCHUNK + chunk)) * H_ + t * 4] = acc;
}

__global__ void context_combine_kernel(float* __restrict__ d_out) {
    const int b = blockIdx.x, t = threadIdx.x;
    float4 s = make_float4(0.f, 0.f, 0.f, 0.f);
    #pragma unroll
    for (int c = 0; c < NCHUNK; c++) {
        float4 p = *(const float4*)&g_ctx_part[((size_t)(b * NCHUNK + c)) * H_ + t * 4];
        s.x += p.x; s.y += p.y; s.z += p.z; s.w += p.w;
    }
    *(float4*)&d_out[b * H_ + t * 4] = s;
}

// ---------------------------------------------------------------------------
extern "C" void kernel_launch(void* const* d_in, const int* in_sizes, int n_in,
                              void* d_out, int out_size) {
    const float* hidden = (const float*)d_in[0];
    const float* E      = (const float*)d_in[1];
    const float* W_w    = (const float*)d_in[2];
    const float* W_b    = (const float*)d_in[3];
    const float* U_w    = (const float*)d_in[4];
    const float* U_b    = (const float*)d_in[5];
    const float* V_w    = (const float*)d_in[6];
    // d_in[7] = V_b cancels under softmax
    float* out = (float*)d_out;

    cudaFuncSetAttribute(score_gemm_mma,
                         cudaFuncAttributeMaxDynamicSharedMemorySize, SMEM_GEMM);

    zero_scores_kernel<<<(B_ * S_ + 255) / 256, 256>>>();
    convert_E_kernel<<<(int)(((size_t)M_ * H_ / 4) / 256), 256>>>(E);
    convert_U_kernel<<<(H_ * H_ / 4) / 256, 256>>>(U_w);
    hproj_kernel<<<dim3(8, B_), 256>>>(hidden, W_w, W_b);
    score_gemm_mma<<<dim3(H_ / 128, M_ / 128), 256, SMEM_GEMM>>>(U_b, V_w);
    softmax_kernel<<<B_, 256>>>(out);
    context_partial_kernel<<<dim3(NCHUNK, B_), 256>>>(E);
    context_combine_kernel<<<B_, 256>>>(out);
}

// round 11
// speedup vs baseline: 1.4528x; 1.4528x over previous
#include <cuda_runtime.h>
#include <cuda_fp16.h>
#include <math.h>
#include <stdint.h>

// ---------------------------------------------------------------------------
// Problem shapes
// ---------------------------------------------------------------------------
#define B_  32
#define S_  2048
#define H_  1024
#define M_  (B_ * S_)
#define NCHUNK 16

// ---------------------------------------------------------------------------
// Device scratch (static: no allocations allowed)
// ---------------------------------------------------------------------------
__device__ float g_hproj[B_ * H_];
__device__ float g_scores[B_ * S_];
__device__ float g_ctx_part[B_ * NCHUNK * H_];
__device__ __half g_Ef16[(size_t)M_ * H_];     // 128 MB
__device__ __half g_Uf16[(size_t)H_ * H_];     // 2 MB

// ---------------------------------------------------------------------------
// PTX helpers (baseline sm_100 ISA: cp.async, ldmatrix, mma.sync)
// ---------------------------------------------------------------------------
__device__ __forceinline__ uint32_t smem_u32(const void* p) {
    uint32_t a;
    asm("{ .reg .u64 t; cvta.to.shared.u64 t, %1; cvt.u32.u64 %0, t; }" : "=r"(a) : "l"(p));
    return a;
}

#define SMEM_SWIZZLE_128B(off) ((off) ^ (((off) >> 3) & 0x70))

__device__ __forceinline__ void cp_async16(uint32_t dst, const void* src) {
    asm volatile("cp.async.cg.shared.global [%0], [%1], 16;" :: "r"(dst), "l"(src));
}
#define CP_COMMIT() asm volatile("cp.async.commit_group;" ::: "memory")
template <int N>
__device__ __forceinline__ void cp_wait_group() {
    asm volatile("cp.async.wait_group %0;" :: "n"(N) : "memory");
}

__device__ __forceinline__ void ldmx4(uint32_t* r, uint32_t a) {
    asm volatile("ldmatrix.sync.aligned.m8n8.x4.shared.b16 {%0,%1,%2,%3}, [%4];"
                 : "=r"(r[0]), "=r"(r[1]), "=r"(r[2]), "=r"(r[3]) : "r"(a));
}
__device__ __forceinline__ void mma16816(float* d, const uint32_t* a, const uint32_t* b) {
    asm volatile(
        "mma.sync.aligned.m16n8k16.row.col.f32.f16.f16.f32 "
        "{%0,%1,%2,%3},{%4,%5,%6,%7},{%8,%9},{%0,%1,%2,%3};"
        : "+f"(d[0]), "+f"(d[1]), "+f"(d[2]), "+f"(d[3])
        : "r"(a[0]), "r"(a[1]), "r"(a[2]), "r"(a[3]), "r"(b[0]), "r"(b[1]));
}

// ---------------------------------------------------------------------------
// Kernel 0: zero score accumulator
// ---------------------------------------------------------------------------
__global__ void zero_scores_kernel() {
    int i = blockIdx.x * blockDim.x + threadIdx.x;
    if (i < B_ * S_) g_scores[i] = 0.0f;
}

// ---------------------------------------------------------------------------
// Converts: E and U -> single fp16 planes
// ---------------------------------------------------------------------------
__global__ void convert_E_kernel(const float* __restrict__ E) {
    size_t i = ((size_t)blockIdx.x * blockDim.x + threadIdx.x) * 4;
    float4 v = *(const float4*)(E + i);
    __half2* d = (__half2*)(g_Ef16 + i);
    d[0] = __floats2half2_rn(v.x, v.y);
    d[1] = __floats2half2_rn(v.z, v.w);
}

__global__ void convert_U_kernel(const float* __restrict__ U) {
    size_t i = ((size_t)blockIdx.x * blockDim.x + threadIdx.x) * 4;
    float4 v = *(const float4*)(U + i);
    __half2* d = (__half2*)(g_Uf16 + i);
    d[0] = __floats2half2_rn(v.x, v.y);
    d[1] = __floats2half2_rn(v.z, v.w);
}

// ---------------------------------------------------------------------------
// Kernel 1: h_proj[b,k] = hidden[b,:] . W_w[k,:] + W_b[k]
// grid (8 k-slices, 32 batches), 256 threads, warp-per-k reduction.
// ---------------------------------------------------------------------------
__global__ void hproj_kernel(const float* __restrict__ hidden,
                             const float* __restrict__ W_w,
                             const float* __restrict__ W_b) {
    int slice = blockIdx.x;
    int b     = blockIdx.y;
    __shared__ float sh[H_];
    for (int i = threadIdx.x; i < H_; i += blockDim.x) sh[i] = hidden[b * H_ + i];
    __syncthreads();
    int warp = threadIdx.x >> 5, lane = threadIdx.x & 31;
    for (int kk = warp; kk < 128; kk += 8) {
        int k = slice * 128 + kk;
        const float* w = W_w + (size_t)k * H_;
        float s = 0.0f;
        #pragma unroll 8
        for (int h = lane; h < H_; h += 32) s += sh[h] * w[h];
        #pragma unroll
        for (int o = 16; o > 0; o >>= 1) s += __shfl_down_sync(0xffffffffu, s, o);
        if (lane == 0) g_hproj[b * H_ + k] = s + W_b[k];
    }
}

// ---------------------------------------------------------------------------
// Kernel 2: fp16 single-MMA score GEMM + fused tanh/V epilogue.
//   C[m,n] = E_f16[m,:] . U_f16[n,:]   (fp32 accumulate)
//   score[m] += sum_n V_w[n] * tanh(C[m,n] + hproj[b,n] + U_b[n])
// Tile 128x128, BK=64, 4-stage cp.async (2 planes/stage), 256 threads
// (8 warps, 4x2 grid, warp tile 32x64), B via ldmatrix.x4.
// ---------------------------------------------------------------------------
#define BKC    64
#define NKCH   (H_ / BKC)         // 16
#define PLANE  16384              // 128 rows x 128 bytes (64 halves)
#define STG_SZ (2 * PLANE)        // A(E), B(U)
#define NSTG   4
#define SMEM_GEMM (NSTG * STG_SZ) // 131072 B

extern __shared__ char dyn_smem[];

__device__ __forceinline__ void gemm_load_stage(uint32_t stg, int chunk,
                                                int m0, int n0, int tid) {
    const size_t kbase = (size_t)chunk * BKC;
    #pragma unroll
    for (int i = 0; i < 4; i++) {
        int p   = tid + i * 256;       // 0..1023
        int r   = p >> 3;              // row 0..127
        int c16 = p & 7;               // 16B piece 0..7
        uint32_t sw = SMEM_SWIZZLE_128B((uint32_t)(r * 128 + c16 * 16));
        size_t ga = (size_t)(m0 + r) * H_ + kbase + c16 * 8;
        size_t gb = (size_t)(n0 + r) * H_ + kbase + c16 * 8;
        cp_async16(stg + 0 * PLANE + sw, g_Ef16 + ga);
        cp_async16(stg + 1 * PLANE + sw, g_Uf16 + gb);
    }
    CP_COMMIT();
}

__global__ void __launch_bounds__(256, 1)
score_gemm_mma(const float* __restrict__ U_b, const float* __restrict__ V_w) {
    __shared__ float hp[128];
    __shared__ float vs[128];
    __shared__ float red[128][2];

    const int tid  = threadIdx.x;
    const int lane = tid & 31;
    const int wid  = tid >> 5;
    const int wm   = wid & 3;          // 4 m-warps, 32 rows each
    const int wn   = wid >> 2;         // 2 n-warps, 64 cols each
    const int n0   = blockIdx.x * 128;
    const int m0   = blockIdx.y * 128;
    const int b    = m0 >> 11;

    const uint32_t sbase = smem_u32(dyn_smem);

    if (tid < 128) {
        hp[tid] = g_hproj[b * H_ + n0 + tid] + U_b[n0 + tid];
        vs[tid] = V_w[n0 + tid];
    }

    float acc[2][8][4];
    #pragma unroll
    for (int mt = 0; mt < 2; mt++)
        #pragma unroll
        for (int nt = 0; nt < 8; nt++)
            #pragma unroll
            for (int q = 0; q < 4; q++) acc[mt][nt][q] = 0.0f;

    // prologue: chunks 0,1,2 into stages 0,1,2
    gemm_load_stage(sbase + 0 * STG_SZ, 0, m0, n0, tid);
    gemm_load_stage(sbase + 1 * STG_SZ, 1, m0, n0, tid);
    gemm_load_stage(sbase + 2 * STG_SZ, 2, m0, n0, tid);

    // A fragment offsets
    const uint32_t offA[2] = {
        SMEM_SWIZZLE_128B((uint32_t)((wm * 32 +  0 + (lane & 15)) * 128 + (lane >> 4) * 16)),
        SMEM_SWIZZLE_128B((uint32_t)((wm * 32 + 16 + (lane & 15)) * 128 + (lane >> 4) * 16))
    };
    // B fragment offsets for ldmatrix.x4: quad t covers n-tiles 2t, 2t+1.
    uint32_t offB4[4];
    #pragma unroll
    for (int t = 0; t < 4; t++) {
        uint32_t row = (uint32_t)(wn * 64 + t * 16 + ((lane >> 4) << 3) + (lane & 7));
        uint32_t piece = (lane >> 3) & 1;
        offB4[t] = SMEM_SWIZZLE_128B(row * 128 + piece * 16);
    }

    for (int c = 0; c < NKCH; c++) {
        if (c < NKCH - 2)       cp_wait_group<2>();
        else if (c == NKCH - 2) cp_wait_group<1>();
        else                    cp_wait_group<0>();
        __syncthreads();
        // Load AFTER the barrier: stage (c+3)%4 held chunk c-1, whose reads all
        // completed before this barrier.
        if (c + 3 < NKCH)
            gemm_load_stage(sbase + ((c + 3) % NSTG) * STG_SZ, c + 3, m0, n0, tid);

        const uint32_t stg = sbase + (uint32_t)((c % NSTG) * STG_SZ);
        #pragma unroll
        for (int kk = 0; kk < 4; kk++) {
            const uint32_t kb = (uint32_t)(kk * 32);
            uint32_t ah[2][4];
            #pragma unroll
            for (int mt = 0; mt < 2; mt++)
                ldmx4(ah[mt], stg + 0 * PLANE + (offA[mt] ^ kb));
            uint32_t bb[4][4];
            #pragma unroll
            for (int t = 0; t < 4; t++)
                ldmx4(bb[t], stg + 1 * PLANE + (offB4[t] ^ kb));
            #pragma unroll
            for (int mt = 0; mt < 2; mt++)
                #pragma unroll
                for (int t = 0; t < 4; t++) {
                    mma16816(acc[mt][2 * t + 0], ah[mt], bb[t] + 0);
                    mma16816(acc[mt][2 * t + 1], ah[mt], bb[t] + 2);
                }
        }
    }

    // Epilogue: tanh + V-weighted reduction.
    // D frag: d0,d1 -> row lane/4, cols 2*(lane&3)+{0,1}; d2,d3 -> row+8.
    float part[2][2] = {{0.f, 0.f}, {0.f, 0.f}};
    #pragma unroll
    for (int mt = 0; mt < 2; mt++)
        #pragma unroll
        for (int nt = 0; nt < 8; nt++) {
            const int c0 = wn * 64 + nt * 8 + 2 * (lane & 3);
            const float* d = acc[mt][nt];
            part[mt][0] += tanhf(d[0] + hp[c0]) * vs[c0]
                         + tanhf(d[1] + hp[c0 + 1]) * vs[c0 + 1];
            part[mt][1] += tanhf(d[2] + hp[c0]) * vs[c0]
                         + tanhf(d[3] + hp[c0 + 1]) * vs[c0 + 1];
        }
    #pragma unroll
    for (int mt = 0; mt < 2; mt++)
        #pragma unroll
        for (int rr = 0; rr < 2; rr++) {
            float p = part[mt][rr];
            p += __shfl_xor_sync(0xffffffffu, p, 1);
            p += __shfl_xor_sync(0xffffffffu, p, 2);
            if ((lane & 3) == 0)
                red[wm * 32 + mt * 16 + rr * 8 + (lane >> 2)][wn] = p;
        }
    __syncthreads();
    if (tid < 128)
        atomicAdd(&g_scores[m0 + tid], red[tid][0] + red[tid][1]);
}

// ---------------------------------------------------------------------------
// Kernel 3: softmax over S per batch
// ---------------------------------------------------------------------------
__global__ void softmax_kernel(float* __restrict__ d_out) {
    const int b = blockIdx.x, tid = threadIdx.x;
    __shared__ float sred[256];
    float loc[8];
    float mx = -1e30f;
    #pragma unroll
    for (int q = 0; q < 8; q++) {
        loc[q] = g_scores[b * S_ + tid + q * 256];
        mx = fmaxf(mx, loc[q]);
    }
    sred[tid] = mx; __syncthreads();
    for (int o = 128; o > 0; o >>= 1) {
        if (tid < o) sred[tid] = fmaxf(sred[tid], sred[tid + o]);
        __syncthreads();
    }
    mx = sred[0]; __syncthreads();
    float sum = 0.0f;
    #pragma unroll
    for (int q = 0; q < 8; q++) { loc[q] = expf(loc[q] - mx); sum += loc[q]; }
    sred[tid] = sum; __syncthreads();
    for (int o = 128; o > 0; o >>= 1) {
        if (tid < o) sred[tid] += sred[tid + o];
        __syncthreads();
    }
    const float inv = 1.0f / sred[0];
    float* attn_out = d_out + B_ * H_;
    #pragma unroll
    for (int q = 0; q < 8; q++) {
        int s = tid + q * 256;
        float a = loc[q] * inv;
        attn_out[b * S_ + s] = a;
        g_scores[b * S_ + s] = a;
    }
}

// ---------------------------------------------------------------------------
// Kernels 4/5: context = attn @ E (partials + deterministic combine)
// ---------------------------------------------------------------------------
__global__ void context_partial_kernel(const float* __restrict__ E) {
    const int chunk = blockIdx.x, b = blockIdx.y, t = threadIdx.x;
    const int s0 = chunk * (S_ / NCHUNK);
    float4 acc = make_float4(0.f, 0.f, 0.f, 0.f);
    const float* base = E + (size_t)(b * S_ + s0) * H_ + t * 4;
    #pragma unroll 4
    for (int s = 0; s < S_ / NCHUNK; s++) {
        float a  = g_scores[b * S_ + s0 + s];
        float4 e = *(const float4*)(base + (size_t)s * H_);
        acc.x = fmaf(a, e.x, acc.x); acc.y = fmaf(a, e.y, acc.y);
        acc.z = fmaf(a, e.z, acc.z); acc.w = fmaf(a, e.w, acc.w);
    }
    *(float4*)&g_ctx_part[((size_t)(b * NCHUNK + chunk)) * H_ + t * 4] = acc;
}

__global__ void context_combine_kernel(float* __restrict__ d_out) {
    const int b = blockIdx.x, t = threadIdx.x;
    float4 s = make_float4(0.f, 0.f, 0.f, 0.f);
    #pragma unroll
    for (int c = 0; c < NCHUNK; c++) {
        float4 p = *(const float4*)&g_ctx_part[((size_t)(b * NCHUNK + c)) * H_ + t * 4];
        s.x += p.x; s.y += p.y; s.z += p.z; s.w += p.w;
    }
    *(float4*)&d_out[b * H_ + t * 4] = s;
}

// ---------------------------------------------------------------------------
extern "C" void kernel_launch(void* const* d_in, const int* in_sizes, int n_in,
                              void* d_out, int out_size) {
    const float* hidden = (const float*)d_in[0];
    const float* E      = (const float*)d_in[1];
    const float* W_w    = (const float*)d_in[2];
    const float* W_b    = (const float*)d_in[3];
    const float* U_w    = (const float*)d_in[4];
    const float* U_b    = (const float*)d_in[5];
    const float* V_w    = (const float*)d_in[6];
    // d_in[7] = V_b cancels under softmax
    float* out = (float*)d_out;

    cudaFuncSetAttribute(score_gemm_mma,
                         cudaFuncAttributeMaxDynamicSharedMemorySize, SMEM_GEMM);

    zero_scores_kernel<<<(B_ * S_ + 255) / 256, 256>>>();
    convert_E_kernel<<<(int)(((size_t)M_ * H_ / 4) / 256), 256>>>(E);
    convert_U_kernel<<<(H_ * H_ / 4) / 256, 256>>>(U_w);
    hproj_kernel<<<dim3(8, B_), 256>>>(hidden, W_w, W_b);
    score_gemm_mma<<<dim3(H_ / 128, M_ / 128), 256, SMEM_GEMM>>>(U_b, V_w);
    softmax_kernel<<<B_, 256>>>(out);
    context_partial_kernel<<<dim3(NCHUNK, B_), 256>>>(E);
    context_combine_kernel<<<B_, 256>>>(out);
}

// round 13
// speedup vs baseline: 1.6429x; 1.1309x over previous
#include <cuda_runtime.h>
#include <cuda_fp16.h>
#include <math.h>
#include <stdint.h>

// ---------------------------------------------------------------------------
// Problem shapes
// ---------------------------------------------------------------------------
#define B_  32
#define S_  2048
#define H_  1024
#define M_  (B_ * S_)
#define NCHUNK 16

// ---------------------------------------------------------------------------
// Device scratch (static: no allocations allowed)
// ---------------------------------------------------------------------------
__device__ float g_hproj[B_ * H_];
__device__ float g_scores[B_ * S_];
__device__ float g_ctx_part[B_ * NCHUNK * H_];
__device__ __half g_Ef16[(size_t)M_ * H_];     // 128 MB
__device__ __half g_Uf16[(size_t)H_ * H_];     // 2 MB

// ---------------------------------------------------------------------------
// PTX helpers (baseline sm_100 ISA: cp.async, ldmatrix, mma.sync)
// ---------------------------------------------------------------------------
__device__ __forceinline__ uint32_t smem_u32(const void* p) {
    uint32_t a;
    asm("{ .reg .u64 t; cvta.to.shared.u64 t, %1; cvt.u32.u64 %0, t; }" : "=r"(a) : "l"(p));
    return a;
}

#define SMEM_SWIZZLE_128B(off) ((off) ^ (((off) >> 3) & 0x70))

__device__ __forceinline__ void cp_async16(uint32_t dst, const void* src) {
    asm volatile("cp.async.cg.shared.global [%0], [%1], 16;" :: "r"(dst), "l"(src));
}
#define CP_COMMIT() asm volatile("cp.async.commit_group;" ::: "memory")
template <int N>
__device__ __forceinline__ void cp_wait_group() {
    asm volatile("cp.async.wait_group %0;" :: "n"(N) : "memory");
}

__device__ __forceinline__ void ldmx4(uint32_t* r, uint32_t a) {
    asm volatile("ldmatrix.sync.aligned.m8n8.x4.shared.b16 {%0,%1,%2,%3}, [%4];"
                 : "=r"(r[0]), "=r"(r[1]), "=r"(r[2]), "=r"(r[3]) : "r"(a));
}
__device__ __forceinline__ void mma16816(float* d, const uint32_t* a, const uint32_t* b) {
    asm volatile(
        "mma.sync.aligned.m16n8k16.row.col.f32.f16.f16.f32 "
        "{%0,%1,%2,%3},{%4,%5,%6,%7},{%8,%9},{%0,%1,%2,%3};"
        : "+f"(d[0]), "+f"(d[1]), "+f"(d[2]), "+f"(d[3])
        : "r"(a[0]), "r"(a[1]), "r"(a[2]), "r"(a[3]), "r"(b[0]), "r"(b[1]));
}

// ---------------------------------------------------------------------------
// Kernel 0: zero score accumulator
// ---------------------------------------------------------------------------
__global__ void zero_scores_kernel() {
    int i = blockIdx.x * blockDim.x + threadIdx.x;
    if (i < B_ * S_) g_scores[i] = 0.0f;
}

// ---------------------------------------------------------------------------
// Converts: E and U -> single fp16 planes
// ---------------------------------------------------------------------------
__global__ void convert_E_kernel(const float* __restrict__ E) {
    size_t i = ((size_t)blockIdx.x * blockDim.x + threadIdx.x) * 4;
    float4 v = *(const float4*)(E + i);
    __half2* d = (__half2*)(g_Ef16 + i);
    d[0] = __floats2half2_rn(v.x, v.y);
    d[1] = __floats2half2_rn(v.z, v.w);
}

__global__ void convert_U_kernel(const float* __restrict__ U) {
    size_t i = ((size_t)blockIdx.x * blockDim.x + threadIdx.x) * 4;
    float4 v = *(const float4*)(U + i);
    __half2* d = (__half2*)(g_Uf16 + i);
    d[0] = __floats2half2_rn(v.x, v.y);
    d[1] = __floats2half2_rn(v.z, v.w);
}

// ---------------------------------------------------------------------------
// Kernel 1: h_proj[b,k] = hidden[b,:] . W_w[k,:] + W_b[k]
// grid (8 k-slices, 32 batches), 256 threads, warp-per-k reduction.
// ---------------------------------------------------------------------------
__global__ void hproj_kernel(const float* __restrict__ hidden,
                             const float* __restrict__ W_w,
                             const float* __restrict__ W_b) {
    int slice = blockIdx.x;
    int b     = blockIdx.y;
    __shared__ float sh[H_];
    for (int i = threadIdx.x; i < H_; i += blockDim.x) sh[i] = hidden[b * H_ + i];
    __syncthreads();
    int warp = threadIdx.x >> 5, lane = threadIdx.x & 31;
    for (int kk = warp; kk < 128; kk += 8) {
        int k = slice * 128 + kk;
        const float* w = W_w + (size_t)k * H_;
        float s = 0.0f;
        #pragma unroll 8
        for (int h = lane; h < H_; h += 32) s += sh[h] * w[h];
        #pragma unroll
        for (int o = 16; o > 0; o >>= 1) s += __shfl_down_sync(0xffffffffu, s, o);
        if (lane == 0) g_hproj[b * H_ + k] = s + W_b[k];
    }
}

// ---------------------------------------------------------------------------
// Kernel 2: fp16 single-MMA score GEMM + fused tanh/V epilogue.
//   C[m,n] = E_f16[m,:] . U_f16[n,:]   (fp32 accumulate)
//   score[m] += sum_n V_w[n] * tanh(C[m,n] + hproj[b,n] + U_b[n])
// Tile 128x128, BK=64, 3-stage cp.async (2 planes/stage, 96 KB), 256 threads,
// 2 CTAs/SM so one CTA's MMA issue overlaps the other's barriers/prologue/
// epilogue (the ~170us non-HMMA overhead measured in R11).
// ---------------------------------------------------------------------------
#define BKC    64
#define NKCH   (H_ / BKC)         // 16
#define PLANE  16384              // 128 rows x 128 bytes (64 halves)
#define STG_SZ (2 * PLANE)        // A(E), B(U)
#define NSTG   3
#define SMEM_GEMM (NSTG * STG_SZ) // 98304 B -> 2 CTAs/SM fit in 228 KB

extern __shared__ char dyn_smem[];

__device__ __forceinline__ void gemm_load_stage(uint32_t stg, int chunk,
                                                int m0, int n0, int tid) {
    const size_t kbase = (size_t)chunk * BKC;
    #pragma unroll
    for (int i = 0; i < 4; i++) {
        int p   = tid + i * 256;       // 0..1023
        int r   = p >> 3;              // row 0..127
        int c16 = p & 7;               // 16B piece 0..7
        uint32_t sw = SMEM_SWIZZLE_128B((uint32_t)(r * 128 + c16 * 16));
        size_t ga = (size_t)(m0 + r) * H_ + kbase + c16 * 8;
        size_t gb = (size_t)(n0 + r) * H_ + kbase + c16 * 8;
        cp_async16(stg + 0 * PLANE + sw, g_Ef16 + ga);
        cp_async16(stg + 1 * PLANE + sw, g_Uf16 + gb);
    }
    CP_COMMIT();
}

__global__ void __launch_bounds__(256, 2)
score_gemm_mma(const float* __restrict__ U_b, const float* __restrict__ V_w) {
    __shared__ float hp[128];
    __shared__ float vs[128];
    __shared__ float red[128][2];

    const int tid  = threadIdx.x;
    const int lane = tid & 31;
    const int wid  = tid >> 5;
    const int wm   = wid & 3;          // 4 m-warps, 32 rows each
    const int wn   = wid >> 2;         // 2 n-warps, 64 cols each
    const int n0   = blockIdx.x * 128;
    const int m0   = blockIdx.y * 128;
    const int b    = m0 >> 11;

    const uint32_t sbase = smem_u32(dyn_smem);

    if (tid < 128) {
        hp[tid] = g_hproj[b * H_ + n0 + tid] + U_b[n0 + tid];
        vs[tid] = V_w[n0 + tid];
    }

    float acc[2][8][4];
    #pragma unroll
    for (int mt = 0; mt < 2; mt++)
        #pragma unroll
        for (int nt = 0; nt < 8; nt++)
            #pragma unroll
            for (int q = 0; q < 4; q++) acc[mt][nt][q] = 0.0f;

    // prologue: chunks 0,1 into stages 0,1
    gemm_load_stage(sbase + 0 * STG_SZ, 0, m0, n0, tid);
    gemm_load_stage(sbase + 1 * STG_SZ, 1, m0, n0, tid);

    // A fragment offsets
    const uint32_t offA[2] = {
        SMEM_SWIZZLE_128B((uint32_t)((wm * 32 +  0 + (lane & 15)) * 128 + (lane >> 4) * 16)),
        SMEM_SWIZZLE_128B((uint32_t)((wm * 32 + 16 + (lane & 15)) * 128 + (lane >> 4) * 16))
    };
    // B fragment offsets for ldmatrix.x4: quad t covers n-tiles 2t, 2t+1.
    uint32_t offB4[4];
    #pragma unroll
    for (int t = 0; t < 4; t++) {
        uint32_t row = (uint32_t)(wn * 64 + t * 16 + ((lane >> 4) << 3) + (lane & 7));
        uint32_t piece = (lane >> 3) & 1;
        offB4[t] = SMEM_SWIZZLE_128B(row * 128 + piece * 16);
    }

    for (int c = 0; c < NKCH; c++) {
        if (c < NKCH - 1) cp_wait_group<1>();   // oldest in-flight (chunk c) done
        else              cp_wait_group<0>();
        __syncthreads();
        // Write stage (c+2)%3 AFTER the barrier: it held chunk c-1, whose reads
        // all completed before this barrier.
        if (c + 2 < NKCH)
            gemm_load_stage(sbase + ((c + 2) % NSTG) * STG_SZ, c + 2, m0, n0, tid);

        const uint32_t stg = sbase + (uint32_t)((c % NSTG) * STG_SZ);
        #pragma unroll
        for (int kk = 0; kk < 4; kk++) {
            const uint32_t kb = (uint32_t)(kk * 32);
            uint32_t ah[2][4];
            #pragma unroll
            for (int mt = 0; mt < 2; mt++)
                ldmx4(ah[mt], stg + 0 * PLANE + (offA[mt] ^ kb));
            uint32_t bb[4][4];
            #pragma unroll
            for (int t = 0; t < 4; t++)
                ldmx4(bb[t], stg + 1 * PLANE + (offB4[t] ^ kb));
            #pragma unroll
            for (int mt = 0; mt < 2; mt++)
                #pragma unroll
                for (int t = 0; t < 4; t++) {
                    mma16816(acc[mt][2 * t + 0], ah[mt], bb[t] + 0);
                    mma16816(acc[mt][2 * t + 1], ah[mt], bb[t] + 2);
                }
        }
    }

    // Epilogue: tanh + V-weighted reduction.
    // D frag: d0,d1 -> row lane/4, cols 2*(lane&3)+{0,1}; d2,d3 -> row+8.
    float part[2][2] = {{0.f, 0.f}, {0.f, 0.f}};
    #pragma unroll
    for (int mt = 0; mt < 2; mt++)
        #pragma unroll
        for (int nt = 0; nt < 8; nt++) {
            const int c0 = wn * 64 + nt * 8 + 2 * (lane & 3);
            const float* d = acc[mt][nt];
            part[mt][0] += tanhf(d[0] + hp[c0]) * vs[c0]
                         + tanhf(d[1] + hp[c0 + 1]) * vs[c0 + 1];
            part[mt][1] += tanhf(d[2] + hp[c0]) * vs[c0]
                         + tanhf(d[3] + hp[c0 + 1]) * vs[c0 + 1];
        }
    #pragma unroll
    for (int mt = 0; mt < 2; mt++)
        #pragma unroll
        for (int rr = 0; rr < 2; rr++) {
            float p = part[mt][rr];
            p += __shfl_xor_sync(0xffffffffu, p, 1);
            p += __shfl_xor_sync(0xffffffffu, p, 2);
            if ((lane & 3) == 0)
                red[wm * 32 + mt * 16 + rr * 8 + (lane >> 2)][wn] = p;
        }
    __syncthreads();
    if (tid < 128)
        atomicAdd(&g_scores[m0 + tid], red[tid][0] + red[tid][1]);
}

// ---------------------------------------------------------------------------
// Kernel 3: softmax over S per batch
// ---------------------------------------------------------------------------
__global__ void softmax_kernel(float* __restrict__ d_out) {
    const int b = blockIdx.x, tid = threadIdx.x;
    __shared__ float sred[256];
    float loc[8];
    float mx = -1e30f;
    #pragma unroll
    for (int q = 0; q < 8; q++) {
        loc[q] = g_scores[b * S_ + tid + q * 256];
        mx = fmaxf(mx, loc[q]);
    }
    sred[tid] = mx; __syncthreads();
    for (int o = 128; o > 0; o >>= 1) {
        if (tid < o) sred[tid] = fmaxf(sred[tid], sred[tid + o]);
        __syncthreads();
    }
    mx = sred[0]; __syncthreads();
    float sum = 0.0f;
    #pragma unroll
    for (int q = 0; q < 8; q++) { loc[q] = expf(loc[q] - mx); sum += loc[q]; }
    sred[tid] = sum; __syncthreads();
    for (int o = 128; o > 0; o >>= 1) {
        if (tid < o) sred[tid] += sred[tid + o];
        __syncthreads();
    }
    const float inv = 1.0f / sred[0];
    float* attn_out = d_out + B_ * H_;
    #pragma unroll
    for (int q = 0; q < 8; q++) {
        int s = tid + q * 256;
        float a = loc[q] * inv;
        attn_out[b * S_ + s] = a;
        g_scores[b * S_ + s] = a;
    }
}

// ---------------------------------------------------------------------------
// Kernels 4/5: context = attn @ E (partials + deterministic combine)
// ---------------------------------------------------------------------------
__global__ void context_partial_kernel(const float* __restrict__ E) {
    const int chunk = blockIdx.x, b = blockIdx.y, t = threadIdx.x;
    const int s0 = chunk * (S_ / NCHUNK);
    float4 acc = make_float4(0.f, 0.f, 0.f, 0.f);
    const float* base = E + (size_t)(b * S_ + s0) * H_ + t * 4;
    #pragma unroll 4
    for (int s = 0; s < S_ / NCHUNK; s++) {
        float a  = g_scores[b * S_ + s0 + s];
        float4 e = *(const float4*)(base + (size_t)s * H_);
        acc.x = fmaf(a, e.x, acc.x); acc.y = fmaf(a, e.y, acc.y);
        acc.z = fmaf(a, e.z, acc.z); acc.w = fmaf(a, e.w, acc.w);
    }
    *(float4*)&g_ctx_part[((size_t)(b * NCHUNK + chunk)) * H_ + t * 4] = acc;
}

__global__ void context_combine_kernel(float* __restrict__ d_out) {
    const int b = blockIdx.x, t = threadIdx.x;
    float4 s = make_float4(0.f, 0.f, 0.f, 0.f);
    #pragma unroll
    for (int c = 0; c < NCHUNK; c++) {
        float4 p = *(const float4*)&g_ctx_part[((size_t)(b * NCHUNK + c)) * H_ + t * 4];
        s.x += p.x; s.y += p.y; s.z += p.z; s.w += p.w;
    }
    *(float4*)&d_out[b * H_ + t * 4] = s;
}

// ---------------------------------------------------------------------------
extern "C" void kernel_launch(void* const* d_in, const int* in_sizes, int n_in,
                              void* d_out, int out_size) {
    const float* hidden = (const float*)d_in[0];
    const float* E      = (const float*)d_in[1];
    const float* W_w    = (const float*)d_in[2];
    const float* W_b    = (const float*)d_in[3];
    const float* U_w    = (const float*)d_in[4];
    const float* U_b    = (const float*)d_in[5];
    const float* V_w    = (const float*)d_in[6];
    // d_in[7] = V_b cancels under softmax
    float* out = (float*)d_out;

    cudaFuncSetAttribute(score_gemm_mma,
                         cudaFuncAttributeMaxDynamicSharedMemorySize, SMEM_GEMM);

    zero_scores_kernel<<<(B_ * S_ + 255) / 256, 256>>>();
    convert_E_kernel<<<(int)(((size_t)M_ * H_ / 4) / 256), 256>>>(E);
    convert_U_kernel<<<(H_ * H_ / 4) / 256, 256>>>(U_w);
    hproj_kernel<<<dim3(8, B_), 256>>>(hidden, W_w, W_b);
    score_gemm_mma<<<dim3(H_ / 128, M_ / 128), 256, SMEM_GEMM>>>(U_b, V_w);
    softmax_kernel<<<B_, 256>>>(out);
    context_partial_kernel<<<dim3(NCHUNK, B_), 256>>>(E);
    context_combine_kernel<<<B_, 256>>>(out);
}

// round 14
// speedup vs baseline: 1.7619x; 1.0724x over previous
#include <cuda_runtime.h>
#include <cuda_fp16.h>
#include <math.h>
#include <stdint.h>

// ---------------------------------------------------------------------------
// Problem shapes
// ---------------------------------------------------------------------------
#define B_  32
#define S_  2048
#define H_  1024
#define M_  (B_ * S_)
#define NCHUNK 16

// ---------------------------------------------------------------------------
// Device scratch (static: no allocations allowed)
// ---------------------------------------------------------------------------
__device__ float g_hproj[B_ * H_];
__device__ float g_scores[B_ * S_];
__device__ float g_ctx_part[B_ * NCHUNK * H_];
__device__ __half g_Ef16[(size_t)M_ * H_];     // 128 MB
__device__ __half g_Uf16[(size_t)H_ * H_];     // 2 MB

// ---------------------------------------------------------------------------
// PTX helpers (baseline sm_100 ISA: cp.async, ldmatrix, mma.sync)
// ---------------------------------------------------------------------------
__device__ __forceinline__ uint32_t smem_u32(const void* p) {
    uint32_t a;
    asm("{ .reg .u64 t; cvta.to.shared.u64 t, %1; cvt.u32.u64 %0, t; }" : "=r"(a) : "l"(p));
    return a;
}

#define SMEM_SWIZZLE_128B(off) ((off) ^ (((off) >> 3) & 0x70))

__device__ __forceinline__ void cp_async16(uint32_t dst, const void* src) {
    asm volatile("cp.async.cg.shared.global [%0], [%1], 16;" :: "r"(dst), "l"(src));
}
#define CP_COMMIT() asm volatile("cp.async.commit_group;" ::: "memory")
template <int N>
__device__ __forceinline__ void cp_wait_group() {
    asm volatile("cp.async.wait_group %0;" :: "n"(N) : "memory");
}

__device__ __forceinline__ void ldmx4(uint32_t* r, uint32_t a) {
    asm volatile("ldmatrix.sync.aligned.m8n8.x4.shared.b16 {%0,%1,%2,%3}, [%4];"
                 : "=r"(r[0]), "=r"(r[1]), "=r"(r[2]), "=r"(r[3]) : "r"(a));
}
__device__ __forceinline__ void mma16816(float* d, const uint32_t* a, const uint32_t* b) {
    asm volatile(
        "mma.sync.aligned.m16n8k16.row.col.f32.f16.f16.f32 "
        "{%0,%1,%2,%3},{%4,%5,%6,%7},{%8,%9},{%0,%1,%2,%3};"
        : "+f"(d[0]), "+f"(d[1]), "+f"(d[2]), "+f"(d[3])
        : "r"(a[0]), "r"(a[1]), "r"(a[2]), "r"(a[3]), "r"(b[0]), "r"(b[1]));
}

// ---------------------------------------------------------------------------
// Fused preamble kernel. Roles by blockIdx.x (all independent, 256 threads):
//   [0, 256)           zero g_scores
//   [256, 1280)        convert U -> fp16
//   [1280, 1536)       hproj (8 k-slices x 32 batches)
//   [1536, 1536+65536) convert E -> fp16
// ---------------------------------------------------------------------------
#define NB_ZERO  256
#define NB_U     1024
#define NB_HP    256
#define NB_E     (M_ * (H_ / 4) / 256)   // 65536
#define NB_PRE   (NB_ZERO + NB_U + NB_HP + NB_E)

__global__ void preamble_kernel(const float* __restrict__ E,
                                const float* __restrict__ hidden,
                                const float* __restrict__ W_w,
                                const float* __restrict__ W_b,
                                const float* __restrict__ U_w) {
    __shared__ float sh[H_];
    const int bid = blockIdx.x;
    const int tid = threadIdx.x;

    if (bid < NB_ZERO) {
        g_scores[bid * 256 + tid] = 0.0f;
    } else if (bid < NB_ZERO + NB_U) {
        size_t i = ((size_t)(bid - NB_ZERO) * 256 + tid) * 4;
        float4 v = *(const float4*)(U_w + i);
        __half2* d = (__half2*)(g_Uf16 + i);
        d[0] = __floats2half2_rn(v.x, v.y);
        d[1] = __floats2half2_rn(v.z, v.w);
    } else if (bid < NB_ZERO + NB_U + NB_HP) {
        const int r     = bid - (NB_ZERO + NB_U);
        const int slice = r & 7;          // 0..7 -> 128 k's
        const int b     = r >> 3;         // 0..31
        for (int i = tid; i < H_; i += 256) sh[i] = hidden[b * H_ + i];
        __syncthreads();
        const int warp = tid >> 5, lane = tid & 31;
        for (int kk = warp; kk < 128; kk += 8) {
            int k = slice * 128 + kk;
            const float* w = W_w + (size_t)k * H_;
            float s = 0.0f;
            #pragma unroll 8
            for (int h = lane; h < H_; h += 32) s += sh[h] * w[h];
            #pragma unroll
            for (int o = 16; o > 0; o >>= 1) s += __shfl_down_sync(0xffffffffu, s, o);
            if (lane == 0) g_hproj[b * H_ + k] = s + W_b[k];
        }
    } else {
        size_t i = ((size_t)(bid - (NB_ZERO + NB_U + NB_HP)) * 256 + tid) * 4;
        float4 v = *(const float4*)(E + i);
        __half2* d = (__half2*)(g_Ef16 + i);
        d[0] = __floats2half2_rn(v.x, v.y);
        d[1] = __floats2half2_rn(v.z, v.w);
    }
}

// ---------------------------------------------------------------------------
// Kernel 2: fp16 single-MMA score GEMM + fused tanh/V epilogue.  (R13, proven)
//   C[m,n] = E_f16[m,:] . U_f16[n,:]   (fp32 accumulate)
//   score[m] += sum_n V_w[n] * tanh(C[m,n] + hproj[b,n] + U_b[n])
// Tile 128x128, BK=64, 3-stage cp.async (96 KB), 256 threads, 2 CTAs/SM.
// ---------------------------------------------------------------------------
#define BKC    64
#define NKCH   (H_ / BKC)         // 16
#define PLANE  16384              // 128 rows x 128 bytes (64 halves)
#define STG_SZ (2 * PLANE)        // A(E), B(U)
#define NSTG   3
#define SMEM_GEMM (NSTG * STG_SZ) // 98304 B -> 2 CTAs/SM

extern __shared__ char dyn_smem[];

__device__ __forceinline__ void gemm_load_stage(uint32_t stg, int chunk,
                                                int m0, int n0, int tid) {
    const size_t kbase = (size_t)chunk * BKC;
    #pragma unroll
    for (int i = 0; i < 4; i++) {
        int p   = tid + i * 256;       // 0..1023
        int r   = p >> 3;              // row 0..127
        int c16 = p & 7;               // 16B piece 0..7
        uint32_t sw = SMEM_SWIZZLE_128B((uint32_t)(r * 128 + c16 * 16));
        size_t ga = (size_t)(m0 + r) * H_ + kbase + c16 * 8;
        size_t gb = (size_t)(n0 + r) * H_ + kbase + c16 * 8;
        cp_async16(stg + 0 * PLANE + sw, g_Ef16 + ga);
        cp_async16(stg + 1 * PLANE + sw, g_Uf16 + gb);
    }
    CP_COMMIT();
}

__global__ void __launch_bounds__(256, 2)
score_gemm_mma(const float* __restrict__ U_b, const float* __restrict__ V_w) {
    __shared__ float hp[128];
    __shared__ float vs[128];
    __shared__ float red[128][2];

    const int tid  = threadIdx.x;
    const int lane = tid & 31;
    const int wid  = tid >> 5;
    const int wm   = wid & 3;          // 4 m-warps, 32 rows each
    const int wn   = wid >> 2;         // 2 n-warps, 64 cols each
    const int n0   = blockIdx.x * 128;
    const int m0   = blockIdx.y * 128;
    const int b    = m0 >> 11;

    const uint32_t sbase = smem_u32(dyn_smem);

    if (tid < 128) {
        hp[tid] = g_hproj[b * H_ + n0 + tid] + U_b[n0 + tid];
        vs[tid] = V_w[n0 + tid];
    }

    float acc[2][8][4];
    #pragma unroll
    for (int mt = 0; mt < 2; mt++)
        #pragma unroll
        for (int nt = 0; nt < 8; nt++)
            #pragma unroll
            for (int q = 0; q < 4; q++) acc[mt][nt][q] = 0.0f;

    // prologue: chunks 0,1 into stages 0,1
    gemm_load_stage(sbase + 0 * STG_SZ, 0, m0, n0, tid);
    gemm_load_stage(sbase + 1 * STG_SZ, 1, m0, n0, tid);

    const uint32_t offA[2] = {
        SMEM_SWIZZLE_128B((uint32_t)((wm * 32 +  0 + (lane & 15)) * 128 + (lane >> 4) * 16)),
        SMEM_SWIZZLE_128B((uint32_t)((wm * 32 + 16 + (lane & 15)) * 128 + (lane >> 4) * 16))
    };
    uint32_t offB4[4];
    #pragma unroll
    for (int t = 0; t < 4; t++) {
        uint32_t row = (uint32_t)(wn * 64 + t * 16 + ((lane >> 4) << 3) + (lane & 7));
        uint32_t piece = (lane >> 3) & 1;
        offB4[t] = SMEM_SWIZZLE_128B(row * 128 + piece * 16);
    }

    for (int c = 0; c < NKCH; c++) {
        if (c < NKCH - 1) cp_wait_group<1>();
        else              cp_wait_group<0>();
        __syncthreads();
        if (c + 2 < NKCH)
            gemm_load_stage(sbase + ((c + 2) % NSTG) * STG_SZ, c + 2, m0, n0, tid);

        const uint32_t stg = sbase + (uint32_t)((c % NSTG) * STG_SZ);
        #pragma unroll
        for (int kk = 0; kk < 4; kk++) {
            const uint32_t kb = (uint32_t)(kk * 32);
            uint32_t ah[2][4];
            #pragma unroll
            for (int mt = 0; mt < 2; mt++)
                ldmx4(ah[mt], stg + 0 * PLANE + (offA[mt] ^ kb));
            uint32_t bb[4][4];
            #pragma unroll
            for (int t = 0; t < 4; t++)
                ldmx4(bb[t], stg + 1 * PLANE + (offB4[t] ^ kb));
            #pragma unroll
            for (int mt = 0; mt < 2; mt++)
                #pragma unroll
                for (int t = 0; t < 4; t++) {
                    mma16816(acc[mt][2 * t + 0], ah[mt], bb[t] + 0);
                    mma16816(acc[mt][2 * t + 1], ah[mt], bb[t] + 2);
                }
        }
    }

    // Epilogue: tanh + V-weighted reduction.
    float part[2][2] = {{0.f, 0.f}, {0.f, 0.f}};
    #pragma unroll
    for (int mt = 0; mt < 2; mt++)
        #pragma unroll
        for (int nt = 0; nt < 8; nt++) {
            const int c0 = wn * 64 + nt * 8 + 2 * (lane & 3);
            const float* d = acc[mt][nt];
            part[mt][0] += tanhf(d[0] + hp[c0]) * vs[c0]
                         + tanhf(d[1] + hp[c0 + 1]) * vs[c0 + 1];
            part[mt][1] += tanhf(d[2] + hp[c0]) * vs[c0]
                         + tanhf(d[3] + hp[c0 + 1]) * vs[c0 + 1];
        }
    #pragma unroll
    for (int mt = 0; mt < 2; mt++)
        #pragma unroll
        for (int rr = 0; rr < 2; rr++) {
            float p = part[mt][rr];
            p += __shfl_xor_sync(0xffffffffu, p, 1);
            p += __shfl_xor_sync(0xffffffffu, p, 2);
            if ((lane & 3) == 0)
                red[wm * 32 + mt * 16 + rr * 8 + (lane >> 2)][wn] = p;
        }
    __syncthreads();
    if (tid < 128)
        atomicAdd(&g_scores[m0 + tid], red[tid][0] + red[tid][1]);
}

// ---------------------------------------------------------------------------
// Kernel 3: softmax over S per batch
// ---------------------------------------------------------------------------
__global__ void softmax_kernel(float* __restrict__ d_out) {
    const int b = blockIdx.x, tid = threadIdx.x;
    __shared__ float sred[256];
    float loc[8];
    float mx = -1e30f;
    #pragma unroll
    for (int q = 0; q < 8; q++) {
        loc[q] = g_scores[b * S_ + tid + q * 256];
        mx = fmaxf(mx, loc[q]);
    }
    sred[tid] = mx; __syncthreads();
    for (int o = 128; o > 0; o >>= 1) {
        if (tid < o) sred[tid] = fmaxf(sred[tid], sred[tid + o]);
        __syncthreads();
    }
    mx = sred[0]; __syncthreads();
    float sum = 0.0f;
    #pragma unroll
    for (int q = 0; q < 8; q++) { loc[q] = expf(loc[q] - mx); sum += loc[q]; }
    sred[tid] = sum; __syncthreads();
    for (int o = 128; o > 0; o >>= 1) {
        if (tid < o) sred[tid] += sred[tid + o];
        __syncthreads();
    }
    const float inv = 1.0f / sred[0];
    float* attn_out = d_out + B_ * H_;
    #pragma unroll
    for (int q = 0; q < 8; q++) {
        int s = tid + q * 256;
        float a = loc[q] * inv;
        attn_out[b * S_ + s] = a;
        g_scores[b * S_ + s] = a;
    }
}

// ---------------------------------------------------------------------------
// Kernel 4: context partials from the fp16 E plane (halves traffic).
// grid (NCHUNK, B), 128 threads; thread t covers h = t*8 .. t*8+7 (16B loads).
// ---------------------------------------------------------------------------
__global__ void context_partial_kernel() {
    const int chunk = blockIdx.x, b = blockIdx.y, t = threadIdx.x;
    const int s0 = chunk * (S_ / NCHUNK);
    float acc[8] = {0.f, 0.f, 0.f, 0.f, 0.f, 0.f, 0.f, 0.f};
    const __half* base = g_Ef16 + (size_t)(b * S_ + s0) * H_ + t * 8;
    #pragma unroll 4
    for (int s = 0; s < S_ / NCHUNK; s++) {
        float a = g_scores[b * S_ + s0 + s];
        uint4 raw = *(const uint4*)(base + (size_t)s * H_);
        const __half2* e2 = (const __half2*)&raw;
        #pragma unroll
        for (int j = 0; j < 4; j++) {
            float2 f = __half22float2(e2[j]);
            acc[2 * j + 0] = fmaf(a, f.x, acc[2 * j + 0]);
            acc[2 * j + 1] = fmaf(a, f.y, acc[2 * j + 1]);
        }
    }
    float* dst = &g_ctx_part[((size_t)(b * NCHUNK + chunk)) * H_ + t * 8];
    *(float4*)(dst + 0) = make_float4(acc[0], acc[1], acc[2], acc[3]);
    *(float4*)(dst + 4) = make_float4(acc[4], acc[5], acc[6], acc[7]);
}

// ---------------------------------------------------------------------------
// Kernel 5: deterministic combine of context partials
// ---------------------------------------------------------------------------
__global__ void context_combine_kernel(float* __restrict__ d_out) {
    const int b = blockIdx.x, t = threadIdx.x;
    float4 s = make_float4(0.f, 0.f, 0.f, 0.f);
    #pragma unroll
    for (int c = 0; c < NCHUNK; c++) {
        float4 p = *(const float4*)&g_ctx_part[((size_t)(b * NCHUNK + c)) * H_ + t * 4];
        s.x += p.x; s.y += p.y; s.z += p.z; s.w += p.w;
    }
    *(float4*)&d_out[b * H_ + t * 4] = s;
}

// ---------------------------------------------------------------------------
extern "C" void kernel_launch(void* const* d_in, const int* in_sizes, int n_in,
                              void* d_out, int out_size) {
    const float* hidden = (const float*)d_in[0];
    const float* E      = (const float*)d_in[1];
    const float* W_w    = (const float*)d_in[2];
    const float* W_b    = (const float*)d_in[3];
    const float* U_w    = (const float*)d_in[4];
    const float* U_b    = (const float*)d_in[5];
    const float* V_w    = (const float*)d_in[6];
    // d_in[7] = V_b cancels under softmax
    float* out = (float*)d_out;

    cudaFuncSetAttribute(score_gemm_mma,
                         cudaFuncAttributeMaxDynamicSharedMemorySize, SMEM_GEMM);

    preamble_kernel<<<NB_PRE, 256>>>(E, hidden, W_w, W_b, U_w);
    score_gemm_mma<<<dim3(H_ / 128, M_ / 128), 256, SMEM_GEMM>>>(U_b, V_w);
    softmax_kernel<<<B_, 256>>>(out);
    context_partial_kernel<<<dim3(NCHUNK, B_), 128>>>();
    context_combine_kernel<<<B_, 256>>>(out);
}

// round 15
// speedup vs baseline: 1.7991x; 1.0211x over previous
#include <cuda_runtime.h>
#include <cuda_fp16.h>
#include <math.h>
#include <stdint.h>

// ---------------------------------------------------------------------------
// Problem shapes
// ---------------------------------------------------------------------------
#define B_  32
#define S_  2048
#define H_  1024
#define M_  (B_ * S_)
#define NCHUNK 64            // s-chunks for context partials (occupancy: 2048 blocks)

// ---------------------------------------------------------------------------
// Device scratch (static: no allocations allowed)
// ---------------------------------------------------------------------------
__device__ float g_hproj[B_ * H_];
__device__ float g_scores[B_ * S_];
__device__ float g_ctx_part[B_ * NCHUNK * H_];
__device__ __half g_Ef16[(size_t)M_ * H_];     // 128 MB
__device__ __half g_Uf16[(size_t)H_ * H_];     // 2 MB

// ---------------------------------------------------------------------------
// PTX helpers (baseline sm_100 ISA: cp.async, ldmatrix, mma.sync)
// ---------------------------------------------------------------------------
__device__ __forceinline__ uint32_t smem_u32(const void* p) {
    uint32_t a;
    asm("{ .reg .u64 t; cvta.to.shared.u64 t, %1; cvt.u32.u64 %0, t; }" : "=r"(a) : "l"(p));
    return a;
}

#define SMEM_SWIZZLE_128B(off) ((off) ^ (((off) >> 3) & 0x70))

__device__ __forceinline__ void cp_async16(uint32_t dst, const void* src) {
    asm volatile("cp.async.cg.shared.global [%0], [%1], 16;" :: "r"(dst), "l"(src));
}
#define CP_COMMIT() asm volatile("cp.async.commit_group;" ::: "memory")
template <int N>
__device__ __forceinline__ void cp_wait_group() {
    asm volatile("cp.async.wait_group %0;" :: "n"(N) : "memory");
}

__device__ __forceinline__ void ldmx4(uint32_t* r, uint32_t a) {
    asm volatile("ldmatrix.sync.aligned.m8n8.x4.shared.b16 {%0,%1,%2,%3}, [%4];"
                 : "=r"(r[0]), "=r"(r[1]), "=r"(r[2]), "=r"(r[3]) : "r"(a));
}
__device__ __forceinline__ void mma16816(float* d, const uint32_t* a, const uint32_t* b) {
    asm volatile(
        "mma.sync.aligned.m16n8k16.row.col.f32.f16.f16.f32 "
        "{%0,%1,%2,%3},{%4,%5,%6,%7},{%8,%9},{%0,%1,%2,%3};"
        : "+f"(d[0]), "+f"(d[1]), "+f"(d[2]), "+f"(d[3])
        : "r"(a[0]), "r"(a[1]), "r"(a[2]), "r"(a[3]), "r"(b[0]), "r"(b[1]));
}

// ---------------------------------------------------------------------------
// Fused preamble kernel. Roles by blockIdx.x (all independent, 256 threads):
//   [0, 256)           zero g_scores
//   [256, 1280)        convert U -> fp16
//   [1280, 1536)       hproj (8 k-slices x 32 batches)
//   [1536, 1536+65536) convert E -> fp16
// ---------------------------------------------------------------------------
#define NB_ZERO  256
#define NB_U     1024
#define NB_HP    256
#define NB_E     (M_ * (H_ / 4) / 256)   // 65536
#define NB_PRE   (NB_ZERO + NB_U + NB_HP + NB_E)

__global__ void preamble_kernel(const float* __restrict__ E,
                                const float* __restrict__ hidden,
                                const float* __restrict__ W_w,
                                const float* __restrict__ W_b,
                                const float* __restrict__ U_w) {
    __shared__ float sh[H_];
    const int bid = blockIdx.x;
    const int tid = threadIdx.x;

    if (bid < NB_ZERO) {
        g_scores[bid * 256 + tid] = 0.0f;
    } else if (bid < NB_ZERO + NB_U) {
        size_t i = ((size_t)(bid - NB_ZERO) * 256 + tid) * 4;
        float4 v = *(const float4*)(U_w + i);
        __half2* d = (__half2*)(g_Uf16 + i);
        d[0] = __floats2half2_rn(v.x, v.y);
        d[1] = __floats2half2_rn(v.z, v.w);
    } else if (bid < NB_ZERO + NB_U + NB_HP) {
        const int r     = bid - (NB_ZERO + NB_U);
        const int slice = r & 7;          // 0..7 -> 128 k's
        const int b     = r >> 3;         // 0..31
        for (int i = tid; i < H_; i += 256) sh[i] = hidden[b * H_ + i];
        __syncthreads();
        const int warp = tid >> 5, lane = tid & 31;
        for (int kk = warp; kk < 128; kk += 8) {
            int k = slice * 128 + kk;
            const float* w = W_w + (size_t)k * H_;
            float s = 0.0f;
            #pragma unroll 8
            for (int h = lane; h < H_; h += 32) s += sh[h] * w[h];
            #pragma unroll
            for (int o = 16; o > 0; o >>= 1) s += __shfl_down_sync(0xffffffffu, s, o);
            if (lane == 0) g_hproj[b * H_ + k] = s + W_b[k];
        }
    } else {
        size_t i = ((size_t)(bid - (NB_ZERO + NB_U + NB_HP)) * 256 + tid) * 4;
        float4 v = *(const float4*)(E + i);
        __half2* d = (__half2*)(g_Ef16 + i);
        d[0] = __floats2half2_rn(v.x, v.y);
        d[1] = __floats2half2_rn(v.z, v.w);
    }
}

// ---------------------------------------------------------------------------
// Kernel 2: fp16 single-MMA score GEMM + fused tanh/V epilogue.  (R13, proven)
//   C[m,n] = E_f16[m,:] . U_f16[n,:]   (fp32 accumulate)
//   score[m] += sum_n V_w[n] * tanh(C[m,n] + hproj[b,n] + U_b[n])
// Tile 128x128, BK=64, 3-stage cp.async (96 KB), 256 threads, 2 CTAs/SM.
// ---------------------------------------------------------------------------
#define BKC    64
#define NKCH   (H_ / BKC)         // 16
#define PLANE  16384              // 128 rows x 128 bytes (64 halves)
#define STG_SZ (2 * PLANE)        // A(E), B(U)
#define NSTG   3
#define SMEM_GEMM (NSTG * STG_SZ) // 98304 B -> 2 CTAs/SM

extern __shared__ char dyn_smem[];

__device__ __forceinline__ void gemm_load_stage(uint32_t stg, int chunk,
                                                int m0, int n0, int tid) {
    const size_t kbase = (size_t)chunk * BKC;
    #pragma unroll
    for (int i = 0; i < 4; i++) {
        int p   = tid + i * 256;       // 0..1023
        int r   = p >> 3;              // row 0..127
        int c16 = p & 7;               // 16B piece 0..7
        uint32_t sw = SMEM_SWIZZLE_128B((uint32_t)(r * 128 + c16 * 16));
        size_t ga = (size_t)(m0 + r) * H_ + kbase + c16 * 8;
        size_t gb = (size_t)(n0 + r) * H_ + kbase + c16 * 8;
        cp_async16(stg + 0 * PLANE + sw, g_Ef16 + ga);
        cp_async16(stg + 1 * PLANE + sw, g_Uf16 + gb);
    }
    CP_COMMIT();
}

__global__ void __launch_bounds__(256, 2)
score_gemm_mma(const float* __restrict__ U_b, const float* __restrict__ V_w) {
    __shared__ float hp[128];
    __shared__ float vs[128];
    __shared__ float red[128][2];

    const int tid  = threadIdx.x;
    const int lane = tid & 31;
    const int wid  = tid >> 5;
    const int wm   = wid & 3;          // 4 m-warps, 32 rows each
    const int wn   = wid >> 2;         // 2 n-warps, 64 cols each
    const int n0   = blockIdx.x * 128;
    const int m0   = blockIdx.y * 128;
    const int b    = m0 >> 11;

    const uint32_t sbase = smem_u32(dyn_smem);

    if (tid < 128) {
        hp[tid] = g_hproj[b * H_ + n0 + tid] + U_b[n0 + tid];
        vs[tid] = V_w[n0 + tid];
    }

    float acc[2][8][4];
    #pragma unroll
    for (int mt = 0; mt < 2; mt++)
        #pragma unroll
        for (int nt = 0; nt < 8; nt++)
            #pragma unroll
            for (int q = 0; q < 4; q++) acc[mt][nt][q] = 0.0f;

    // prologue: chunks 0,1 into stages 0,1
    gemm_load_stage(sbase + 0 * STG_SZ, 0, m0, n0, tid);
    gemm_load_stage(sbase + 1 * STG_SZ, 1, m0, n0, tid);

    const uint32_t offA[2] = {
        SMEM_SWIZZLE_128B((uint32_t)((wm * 32 +  0 + (lane & 15)) * 128 + (lane >> 4) * 16)),
        SMEM_SWIZZLE_128B((uint32_t)((wm * 32 + 16 + (lane & 15)) * 128 + (lane >> 4) * 16))
    };
    uint32_t offB4[4];
    #pragma unroll
    for (int t = 0; t < 4; t++) {
        uint32_t row = (uint32_t)(wn * 64 + t * 16 + ((lane >> 4) << 3) + (lane & 7));
        uint32_t piece = (lane >> 3) & 1;
        offB4[t] = SMEM_SWIZZLE_128B(row * 128 + piece * 16);
    }

    for (int c = 0; c < NKCH; c++) {
        if (c < NKCH - 1) cp_wait_group<1>();
        else              cp_wait_group<0>();
        __syncthreads();
        if (c + 2 < NKCH)
            gemm_load_stage(sbase + ((c + 2) % NSTG) * STG_SZ, c + 2, m0, n0, tid);

        const uint32_t stg = sbase + (uint32_t)((c % NSTG) * STG_SZ);
        #pragma unroll
        for (int kk = 0; kk < 4; kk++) {
            const uint32_t kb = (uint32_t)(kk * 32);
            uint32_t ah[2][4];
            #pragma unroll
            for (int mt = 0; mt < 2; mt++)
                ldmx4(ah[mt], stg + 0 * PLANE + (offA[mt] ^ kb));
            uint32_t bb[4][4];
            #pragma unroll
            for (int t = 0; t < 4; t++)
                ldmx4(bb[t], stg + 1 * PLANE + (offB4[t] ^ kb));
            #pragma unroll
            for (int mt = 0; mt < 2; mt++)
                #pragma unroll
                for (int t = 0; t < 4; t++) {
                    mma16816(acc[mt][2 * t + 0], ah[mt], bb[t] + 0);
                    mma16816(acc[mt][2 * t + 1], ah[mt], bb[t] + 2);
                }
        }
    }

    // Epilogue: tanh + V-weighted reduction.
    float part[2][2] = {{0.f, 0.f}, {0.f, 0.f}};
    #pragma unroll
    for (int mt = 0; mt < 2; mt++)
        #pragma unroll
        for (int nt = 0; nt < 8; nt++) {
            const int c0 = wn * 64 + nt * 8 + 2 * (lane & 3);
            const float* d = acc[mt][nt];
            part[mt][0] += tanhf(d[0] + hp[c0]) * vs[c0]
                         + tanhf(d[1] + hp[c0 + 1]) * vs[c0 + 1];
            part[mt][1] += tanhf(d[2] + hp[c0]) * vs[c0]
                         + tanhf(d[3] + hp[c0 + 1]) * vs[c0 + 1];
        }
    #pragma unroll
    for (int mt = 0; mt < 2; mt++)
        #pragma unroll
        for (int rr = 0; rr < 2; rr++) {
            float p = part[mt][rr];
            p += __shfl_xor_sync(0xffffffffu, p, 1);
            p += __shfl_xor_sync(0xffffffffu, p, 2);
            if ((lane & 3) == 0)
                red[wm * 32 + mt * 16 + rr * 8 + (lane >> 2)][wn] = p;
        }
    __syncthreads();
    if (tid < 128)
        atomicAdd(&g_scores[m0 + tid], red[tid][0] + red[tid][1]);
}

// ---------------------------------------------------------------------------
// Kernel 3: softmax over S per batch
// ---------------------------------------------------------------------------
__global__ void softmax_kernel(float* __restrict__ d_out) {
    const int b = blockIdx.x, tid = threadIdx.x;
    __shared__ float sred[256];
    float loc[8];
    float mx = -1e30f;
    #pragma unroll
    for (int q = 0; q < 8; q++) {
        loc[q] = g_scores[b * S_ + tid + q * 256];
        mx = fmaxf(mx, loc[q]);
    }
    sred[tid] = mx; __syncthreads();
    for (int o = 128; o > 0; o >>= 1) {
        if (tid < o) sred[tid] = fmaxf(sred[tid], sred[tid + o]);
        __syncthreads();
    }
    mx = sred[0]; __syncthreads();
    float sum = 0.0f;
    #pragma unroll
    for (int q = 0; q < 8; q++) { loc[q] = expf(loc[q] - mx); sum += loc[q]; }
    sred[tid] = sum; __syncthreads();
    for (int o = 128; o > 0; o >>= 1) {
        if (tid < o) sred[tid] += sred[tid + o];
        __syncthreads();
    }
    const float inv = 1.0f / sred[0];
    float* attn_out = d_out + B_ * H_;
    #pragma unroll
    for (int q = 0; q < 8; q++) {
        int s = tid + q * 256;
        float a = loc[q] * inv;
        attn_out[b * S_ + s] = a;
        g_scores[b * S_ + s] = a;
    }
}

// ---------------------------------------------------------------------------
// Kernel 4: context partials from the fp16 E plane.
// grid (NCHUNK=64, B), 128 threads; thread t covers h = t*8..t*8+7 (16B loads).
// 2048 blocks -> ~14 CTAs/SM: enough MLP to approach HBM bandwidth.
// ---------------------------------------------------------------------------
__global__ void context_partial_kernel() {
    const int chunk = blockIdx.x, b = blockIdx.y, t = threadIdx.x;
    const int s0 = chunk * (S_ / NCHUNK);      // 32 s-values per chunk
    float acc[8] = {0.f, 0.f, 0.f, 0.f, 0.f, 0.f, 0.f, 0.f};
    const __half* base = g_Ef16 + (size_t)(b * S_ + s0) * H_ + t * 8;
    #pragma unroll 8
    for (int s = 0; s < S_ / NCHUNK; s++) {
        float a = g_scores[b * S_ + s0 + s];
        uint4 raw = *(const uint4*)(base + (size_t)s * H_);
        const __half2* e2 = (const __half2*)&raw;
        #pragma unroll
        for (int j = 0; j < 4; j++) {
            float2 f = __half22float2(e2[j]);
            acc[2 * j + 0] = fmaf(a, f.x, acc[2 * j + 0]);
            acc[2 * j + 1] = fmaf(a, f.y, acc[2 * j + 1]);
        }
    }
    float* dst = &g_ctx_part[((size_t)(b * NCHUNK + chunk)) * H_ + t * 8];
    *(float4*)(dst + 0) = make_float4(acc[0], acc[1], acc[2], acc[3]);
    *(float4*)(dst + 4) = make_float4(acc[4], acc[5], acc[6], acc[7]);
}

// ---------------------------------------------------------------------------
// Kernel 5: deterministic combine of context partials
// ---------------------------------------------------------------------------
__global__ void context_combine_kernel(float* __restrict__ d_out) {
    const int b = blockIdx.x, t = threadIdx.x;
    float4 s = make_float4(0.f, 0.f, 0.f, 0.f);
    #pragma unroll 8
    for (int c = 0; c < NCHUNK; c++) {
        float4 p = *(const float4*)&g_ctx_part[((size_t)(b * NCHUNK + c)) * H_ + t * 4];
        s.x += p.x; s.y += p.y; s.z += p.z; s.w += p.w;
    }
    *(float4*)&d_out[b * H_ + t * 4] = s;
}

// ---------------------------------------------------------------------------
extern "C" void kernel_launch(void* const* d_in, const int* in_sizes, int n_in,
                              void* d_out, int out_size) {
    const float* hidden = (const float*)d_in[0];
    const float* E      = (const float*)d_in[1];
    const float* W_w    = (const float*)d_in[2];
    const float* W_b    = (const float*)d_in[3];
    const float* U_w    = (const float*)d_in[4];
    const float* U_b    = (const float*)d_in[5];
    const float* V_w    = (const float*)d_in[6];
    // d_in[7] = V_b cancels under softmax
    float* out = (float*)d_out;

    cudaFuncSetAttribute(score_gemm_mma,
                         cudaFuncAttributeMaxDynamicSharedMemorySize, SMEM_GEMM);

    preamble_kernel<<<NB_PRE, 256>>>(E, hidden, W_w, W_b, U_w);
    score_gemm_mma<<<dim3(H_ / 128, M_ / 128), 256, SMEM_GEMM>>>(U_b, V_w);
    softmax_kernel<<<B_, 256>>>(out);
    context_partial_kernel<<<dim3(NCHUNK, B_), 128>>>();
    context_combine_kernel<<<B_, 256>>>(out);
}